// round 16
// baseline (speedup 1.0000x reference)
#include <cuda_runtime.h>

// ---------------- problem constants ----------------
#define U_CNT 100000
#define SI_CNT 50000
#define TI_CNT 40000
#define DD 64
#define BB 8192
#define NS (U_CNT + SI_CNT)   // 150000 rows in source graph
#define NT (U_CNT + TI_CNT)   // 140000 rows in target graph
#define NROWS (NS + NT)       // 290000
#define NSW ((NS + 31) / 32)
#define NTW ((NT + 31) / 32)
#define NW_TOT (NSW + NTW)
#define SLOTS 64
#define MAXROWS 49280         // >= max unique active rows
#define CAP 128               // per-row bucket capacity
#define ROW_BLOCKS ((MAXROWS + 7) / 8)
#define DIS_BLOCKS ((MAXROWS + 7) / 8)
#define LOSS_BLOCKS (BB / 8)

// ---------------- device scratch (zero-init at load; self-cleaned each run) ----------------
// g_agg_* now hold the FINAL propagated embedding 0.5*(e0 + A@e0) for active rows
__device__ float g_agg_s_int[(size_t)NS * DD];
__device__ float g_agg_s_pop[(size_t)NS * DD];
__device__ float g_agg_t_int[(size_t)NT * DD];
__device__ float g_agg_t_pop[(size_t)NT * DD];
__device__ unsigned g_need_s[NSW];
__device__ unsigned g_need_t[NTW];
__device__ double g_accs[12 * SLOTS];
__device__ int g_cnts[3 * SLOTS];
__device__ unsigned g_done = 0;
__device__ int g_nrows = 0;
__device__ int g_rowlist[MAXROWS];
__device__ int g_slot[NROWS];
__device__ int g_next[MAXROWS];
__device__ int4 g_erec[(size_t)MAXROWS * CAP];

// ---------------- helpers ----------------
__device__ __forceinline__ float wred(float v) {
#pragma unroll
    for (int o = 16; o; o >>= 1) v += __shfl_xor_sync(0xffffffffu, v, o);
    return v;
}
__device__ __forceinline__ float hred16(float v) {
#pragma unroll
    for (int o = 8; o; o >>= 1) v += __shfl_xor_sync(0xffffffffu, v, o);
    return v;
}
__device__ __forceinline__ double wredd(double v) {
#pragma unroll
    for (int o = 16; o; o >>= 1) v += __shfl_xor_sync(0xffffffffu, v, o);
    return v;
}
__device__ __forceinline__ int wredi(int v) {
#pragma unroll
    for (int o = 16; o; o >>= 1) v += __shfl_xor_sync(0xffffffffu, v, o);
    return v;
}
__device__ __forceinline__ float lsig(float x) {
    return fminf(x, 0.0f) - log1pf(expf(-fabsf(x)));
}

// warp-aggregated rowlist append (newly-set rows only; unique per row)
__device__ __forceinline__ void append_row(bool newset, int gr) {
    unsigned m = __ballot_sync(0xffffffffu, newset);
    if (!m) return;
    int lane = threadIdx.x & 31;
    int leader = __ffs(m) - 1;
    int base = 0;
    if (lane == leader) base = atomicAdd(&g_nrows, __popc(m));
    base = __shfl_sync(0xffffffffu, base, leader);
    if (newset) {
        int pos = base + __popc(m & ((1u << lane) - 1u));
        g_rowlist[pos] = gr;
        g_slot[gr] = pos;
    }
}

// ---------------- kernels ----------------
__global__ void k_bitmap(const int* __restrict__ user, const int* __restrict__ sp,
                         const int* __restrict__ sn, const int* __restrict__ tp,
                         const int* __restrict__ tn) {
    int i = blockIdx.x * blockDim.x + threadIdx.x;
    int which = i / BB, j = i - which * BB;
    if (which == 0) {
        int u = user[j];
        unsigned bit = 1u << (u & 31);
        unsigned olds = atomicOr(&g_need_s[(unsigned)u >> 5], bit);
        unsigned oldt = atomicOr(&g_need_t[(unsigned)u >> 5], bit);
        append_row(!(olds & bit), u);
        append_row(!(oldt & bit), u + NS);
    } else if (which == 1) {
        int r = U_CNT + sp[j];
        unsigned bit = 1u << (r & 31);
        unsigned old = atomicOr(&g_need_s[(unsigned)r >> 5], bit);
        append_row(!(old & bit), r);
    } else if (which == 2) {
        int r = U_CNT + sn[j];
        unsigned bit = 1u << (r & 31);
        unsigned old = atomicOr(&g_need_s[(unsigned)r >> 5], bit);
        append_row(!(old & bit), r);
    } else if (which == 3) {
        int r = U_CNT + tp[j];
        unsigned bit = 1u << (r & 31);
        unsigned old = atomicOr(&g_need_t[(unsigned)r >> 5], bit);
        append_row(!(old & bit), r + NS);
    } else {
        int r = U_CNT + tn[j];
        unsigned bit = 1u << (r & 31);
        unsigned old = atomicOr(&g_need_t[(unsigned)r >> 5], bit);
        append_row(!(old & bit), r + NS);
    }
}

// scatter: 4 edges/thread; ALL 5 vector loads issued up front (MLP=5)
__global__ void __launch_bounds__(256) k_scatter(
    const int* __restrict__ rows_s, const int* __restrict__ cols_s,
    const float* __restrict__ vals_s, const float* __restrict__ dsi,
    const float* __restrict__ dsp,
    const int* __restrict__ rows_t, const int* __restrict__ cols_t,
    const float* __restrict__ vals_t, const float* __restrict__ dti,
    const float* __restrict__ dtp,
    int nnz_s, int nnz_t, int blocks_s) {

    bool is_s = (int)blockIdx.x < blocks_s;
    int bblk = is_s ? blockIdx.x : blockIdx.x - blocks_s;
    int nnz = is_s ? nnz_s : nnz_t;
    const int* __restrict__ rows = is_s ? rows_s : rows_t;
    const int* __restrict__ cols = is_s ? cols_s : cols_t;
    const float* __restrict__ vals = is_s ? vals_s : vals_t;
    const float* __restrict__ dint = is_s ? dsi : dti;
    const float* __restrict__ dpop = is_s ? dsp : dtp;
    const unsigned* __restrict__ need = is_s ? g_need_s : g_need_t;
    int gbase = is_s ? 0 : NS;

    int i4 = (bblk * 256 + threadIdx.x) * 4;
    if (i4 + 4 <= nnz) {
        int4 r4 = *(const int4*)(rows + i4);
        int4 c4 = *(const int4*)(cols + i4);
        float4 v4 = *(const float4*)(vals + i4);
        float4 di4 = *(const float4*)(dint + i4);
        float4 dp4 = *(const float4*)(dpop + i4);
        bool act[4];
        act[0] = (need[(unsigned)r4.x >> 5] >> (r4.x & 31)) & 1u;
        act[1] = (need[(unsigned)r4.y >> 5] >> (r4.y & 31)) & 1u;
        act[2] = (need[(unsigned)r4.z >> 5] >> (r4.z & 31)) & 1u;
        act[3] = (need[(unsigned)r4.w >> 5] >> (r4.w & 31)) & 1u;
#pragma unroll
        for (int k = 0; k < 4; k++) {
            if (!act[k]) continue;
            int slot = g_slot[(&r4.x)[k] + gbase];
            int pos = atomicAdd(&g_next[slot], 1);
            if (pos < CAP) {
                int4 rec;
                rec.x = (&c4.x)[k];
                rec.y = __float_as_int((&v4.x)[k] * (&di4.x)[k]);
                rec.z = __float_as_int((&v4.x)[k] * (&dp4.x)[k]);
                rec.w = 0;
                g_erec[(size_t)slot * CAP + pos] = rec;
            }
        }
    } else {
        for (int k = 0; k < 4; k++) {
            int i = i4 + k;
            if (i >= nnz) break;
            int r = rows[i];
            if (!((need[(unsigned)r >> 5] >> (r & 31)) & 1u)) continue;
            int slot = g_slot[r + gbase];
            int pos = atomicAdd(&g_next[slot], 1);
            if (pos < CAP) {
                float v = vals[i];
                int4 rec;
                rec.x = cols[i];
                rec.y = __float_as_int(v * dint[i]);
                rec.z = __float_as_int(v * dpop[i]);
                rec.w = 0;
                g_erec[(size_t)slot * CAP + pos] = rec;
            }
        }
    }
}

// fused: row aggregation (stores FINAL 0.5*(emb+agg)) + dis + bitmap clean
__global__ void __launch_bounds__(256) k_rows(
    const float* __restrict__ su_i, const float* __restrict__ si_i,
    const float* __restrict__ su_p, const float* __restrict__ si_p,
    const float* __restrict__ tu_i, const float* __restrict__ ti_i,
    const float* __restrict__ tu_p, const float* __restrict__ ti_p) {

    int lane = threadIdx.x & 31;
    int wid = threadIdx.x >> 5;

    if ((int)blockIdx.x >= ROW_BLOCKS) {
        // ---- dis blocks: masked-L1 over rowlist + bitmap clear ----
        int db = blockIdx.x - ROW_BLOCKS;
        {
            int ci = db * 256 + threadIdx.x;
            if (ci < NSW) g_need_s[ci] = 0u;
            else if (ci < NW_TOT) g_need_t[ci - NSW] = 0u;
        }
        int gw = db * 8 + wid;
        if (gw >= g_nrows) return;
        int gr = g_rowlist[gw];
        int slot = gw & (SLOTS - 1);
        if (gr < U_CNT) {
            int rr = gr;
            float2 a = ((const float2*)(su_i + (size_t)rr * DD))[lane];
            float2 b = ((const float2*)(su_p + (size_t)rr * DD))[lane];
            float2 cc = ((const float2*)(tu_i + (size_t)rr * DD))[lane];
            float2 d = ((const float2*)(tu_p + (size_t)rr * DD))[lane];
            float s1 = wred(fabsf(a.x - b.x) + fabsf(a.y - b.y));
            float s2 = wred(fabsf(cc.x - d.x) + fabsf(cc.y - d.y));
            if (lane == 0) {
                atomicAdd(&g_accs[8 * SLOTS + slot], (double)s1);
                atomicAdd(&g_accs[10 * SLOTS + slot], (double)s2);
                atomicAdd(&g_cnts[0 * SLOTS + slot], 1);
            }
        } else if (gr < NS) {
            int it = gr - U_CNT;
            float2 a = ((const float2*)(si_i + (size_t)it * DD))[lane];
            float2 b = ((const float2*)(si_p + (size_t)it * DD))[lane];
            float s = wred(fabsf(a.x - b.x) + fabsf(a.y - b.y));
            if (lane == 0) {
                atomicAdd(&g_accs[9 * SLOTS + slot], (double)s);
                atomicAdd(&g_cnts[1 * SLOTS + slot], 1);
            }
        } else if (gr >= NS + U_CNT) {
            int it = gr - NS - U_CNT;
            float2 a = ((const float2*)(ti_i + (size_t)it * DD))[lane];
            float2 b = ((const float2*)(ti_p + (size_t)it * DD))[lane];
            float s = wred(fabsf(a.x - b.x) + fabsf(a.y - b.y));
            if (lane == 0) {
                atomicAdd(&g_accs[11 * SLOTS + slot], (double)s);
                atomicAdd(&g_cnts[2 * SLOTS + slot], 1);
            }
        }
        return;
    }

    // ---- row aggregation blocks (proven gather loop) ----
    int gw = blockIdx.x * 8 + wid;
    if (gw >= g_nrows) return;
    int half = lane >> 4, sub = lane & 15;

    int gr = g_rowlist[gw];
    bool is_s = gr < NS;
    int row = is_s ? gr : gr - NS;
    int cnt = min(g_next[gw], CAP);
    if (lane == 0) g_next[gw] = 0;   // self-clean for next replay
    const int4* __restrict__ bucket = g_erec + (size_t)gw * CAP;

    const float* u_tab = is_s ? (half ? su_p : su_i) : (half ? tu_p : tu_i);
    const float* i_tab = is_s ? (half ? si_p : si_i) : (half ? ti_p : ti_i);
    float* agg = is_s ? (half ? g_agg_s_pop : g_agg_s_int)
                      : (half ? g_agg_t_pop : g_agg_t_int);

    // own-row embedding slice (for final 0.5*(emb+agg) store)
    const float* self_tab = (row < U_CNT) ? u_tab : i_tab;
    int self_r = (row < U_CNT) ? row : row - U_CNT;
    float4 eself = __ldg(((const float4*)(self_tab + (size_t)self_r * DD)) + sub);

    float4 acc = make_float4(0.f, 0.f, 0.f, 0.f);

    for (int chunk = 0; chunk < cnt; chunk += 32) {
        int nc = min(32, cnt - chunk);
        int4 rec = (lane < nc) ? bucket[chunk + lane] : make_int4(0, 0, 0, 0);
        int e = 0;
        for (; e + 4 <= nc; e += 4) {
#pragma unroll
            for (int j = 0; j < 4; j++) {
                int s = e + j;
                int c = __shfl_sync(0xffffffffu, rec.x, s);
                int wz = __shfl_sync(0xffffffffu, rec.y, s);
                int ww = __shfl_sync(0xffffffffu, rec.z, s);
                float w = __int_as_float(half ? ww : wz);
                const float* tab = (c < U_CNT) ? u_tab : i_tab;
                int cr = (c < U_CNT) ? c : c - U_CNT;
                float4 ev = __ldg(((const float4*)(tab + (size_t)cr * DD)) + sub);
                acc.x += w * ev.x; acc.y += w * ev.y;
                acc.z += w * ev.z; acc.w += w * ev.w;
            }
        }
        for (; e < nc; e++) {
            int c = __shfl_sync(0xffffffffu, rec.x, e);
            int wz = __shfl_sync(0xffffffffu, rec.y, e);
            int ww = __shfl_sync(0xffffffffu, rec.z, e);
            float w = __int_as_float(half ? ww : wz);
            const float* tab = (c < U_CNT) ? u_tab : i_tab;
            int cr = (c < U_CNT) ? c : c - U_CNT;
            float4 ev = __ldg(((const float4*)(tab + (size_t)cr * DD)) + sub);
            acc.x += w * ev.x; acc.y += w * ev.y;
            acc.z += w * ev.z; acc.w += w * ev.w;
        }
    }
    // store final propagated embedding 0.5*(e0 + A@e0)
    float4 outv = make_float4(0.5f * (eself.x + acc.x), 0.5f * (eself.y + acc.y),
                              0.5f * (eself.z + acc.z), 0.5f * (eself.w + acc.w));
    ((float4*)(agg + (size_t)row * DD))[sub] = outv;
}

// loss: warp per sample, half-warp per factor; agg arrays now hold the FINAL
// propagated embeddings -> only 6 row-gathers per half-warp (was 12).
__global__ void __launch_bounds__(256) k_loss_final(
    const int* __restrict__ user, const int* __restrict__ spi,
    const int* __restrict__ sni, const int* __restrict__ tpi,
    const int* __restrict__ tni,
    const unsigned* __restrict__ mask_s, const unsigned* __restrict__ mask_t,
    const float* __restrict__ su_i, const float* __restrict__ si_i,
    const float* __restrict__ tu_i, const float* __restrict__ ti_i,
    const float* __restrict__ su_p, const float* __restrict__ si_p,
    const float* __restrict__ tu_p, const float* __restrict__ ti_p,
    float* __restrict__ out) {

    int lane = threadIdx.x & 31;
    int wid = threadIdx.x >> 5;
    int half = lane >> 4, sub = lane & 15;
    __shared__ double s_rows[12];
    __shared__ int s_cnt[3];
    __shared__ int s_last;

    {
        int w = blockIdx.x * 8 + wid;
        int u = user[w], ps = spi[w], ns = sni[w], pt = tpi[w], nt = tni[w];

        const float* aggS = half ? g_agg_s_pop : g_agg_s_int;
        const float* aggT = half ? g_agg_t_pop : g_agg_t_int;

#define GET4(t, row) __ldg(((const float4*)((t) + (size_t)(row) * DD)) + sub)
        // 6 independent float4 gathers (final embeddings)
        float4 us = GET4(aggS, u);
        float4 ut = GET4(aggT, u);
        float4 ip = GET4(aggS, U_CNT + ps);
        float4 in_ = GET4(aggS, U_CNT + ns);
        float4 jp = GET4(aggT, U_CNT + pt);
        float4 jn = GET4(aggT, U_CNT + nt);
#undef GET4
        auto d4 = [](float4 a, float4 b) {
            return a.x * b.x + a.y * b.y + a.z * b.z + a.w * b.w;
        };

        float sp = hred16(d4(us, ip));
        float sn = hred16(d4(us, in_));
        float tp = hred16(d4(ut, jp));
        float tn = hred16(d4(ut, jn));

        float sp_p = __shfl_sync(0xffffffffu, sp, 16);
        float sn_p = __shfl_sync(0xffffffffu, sn, 16);
        float tp_p = __shfl_sync(0xffffffffu, tp, 16);
        float tn_p = __shfl_sync(0xffffffffu, tn, 16);

        if (lane == 0) {
            float sp_i = sp, sn_i = sn, tp_i = tp, tn_i = tn;
            int slot = w & (SLOTS - 1);
            float mS = (mask_s[w] != 0u) ? 1.f : 0.f;
            float mT = (mask_t[w] != 0u) ? 1.f : 0.f;

            float t0 = mS * lsig(sp_i - sn_i);
            float t3 = mT * lsig(tp_i - tn_i);
            float xs = sn_p - sp_p;
            float cs = log1pf(expf(-fabsf(xs)));
            float t12 = mS * fminf(xs, 0.f) + (1.f - mS) * fminf(-xs, 0.f) - cs;
            float xt = tn_p - tp_p;
            float ct = log1pf(expf(-fabsf(xt)));
            float t45 = mT * fminf(xt, 0.f) + (1.f - mT) * fminf(-xt, 0.f) - ct;
            float t6 = lsig((sp_i + sp_p) - (sn_i + sn_p));
            float t7 = lsig((tp_i + tp_p) - (tn_i + tn_p));

            atomicAdd(&g_accs[0 * SLOTS + slot], (double)t0);
            atomicAdd(&g_accs[1 * SLOTS + slot], (double)t12);
            atomicAdd(&g_accs[3 * SLOTS + slot], (double)t3);
            atomicAdd(&g_accs[4 * SLOTS + slot], (double)t45);
            atomicAdd(&g_accs[6 * SLOTS + slot], (double)t6);
            atomicAdd(&g_accs[7 * SLOTS + slot], (double)t7);
        }
    }

    // ---- last-block final reduction + state cleanup ----
    __syncthreads();
    if (threadIdx.x == 0) {
        __threadfence();
        unsigned t = atomicInc(&g_done, gridDim.x - 1);
        s_last = (t == gridDim.x - 1) ? 1 : 0;
    }
    __syncthreads();
    if (!s_last) return;

    {
        double v = g_accs[wid * SLOTS + lane] + g_accs[wid * SLOTS + 32 + lane];
        v = wredd(v);
        if (lane == 0) s_rows[wid] = v;
        if (wid < 4) {
            int row = wid + 8;
            double v2 = g_accs[row * SLOTS + lane] + g_accs[row * SLOTS + 32 + lane];
            v2 = wredd(v2);
            if (lane == 0) s_rows[row] = v2;
        }
        if (wid >= 5 && wid < 8) {
            int cr = wid - 5;
            int cv = g_cnts[cr * SLOTS + lane] + g_cnts[cr * SLOTS + 32 + lane];
            cv = wredi(cv);
            if (lane == 0) s_cnt[cr] = cv;
        }
    }
    __syncthreads();
    for (int i = threadIdx.x; i < 12 * SLOTS; i += blockDim.x) g_accs[i] = 0.0;
    for (int i = threadIdx.x; i < 3 * SLOTS; i += blockDim.x) g_cnts[i] = 0;
    if (threadIdx.x == 0) {
        g_nrows = 0;
        double Bn = (double)BB;
        double li_s = -s_rows[0] / Bn, lp_s = -(s_rows[1] + s_rows[2]) / Bn;
        double li_t = -s_rows[3] / Bn, lp_t = -(s_rows[4] + s_rows[5]) / Bn;
        double lt_s = -s_rows[6] / Bn, lt_t = -s_rows[7] / Bn;
        double cu = (double)(s_cnt[0] > 1 ? s_cnt[0] : 1);
        double cs = (double)(s_cnt[1] > 1 ? s_cnt[1] : 1);
        double ct = (double)(s_cnt[2] > 1 ? s_cnt[2] : 1);
        double dis = s_rows[8] / (cu * DD) + s_rows[9] / (cs * DD)
                   + s_rows[10] / (cu * DD) + s_rows[11] / (ct * DD);
        double loss = lt_s + lt_t + 0.1 * (li_s + li_t) + 0.1 * (lp_s + lp_t) - 0.01 * dis;
        out[0] = (float)loss;
    }
}

// ---------------- launch ----------------
extern "C" void kernel_launch(void* const* d_in, const int* in_sizes, int n_in,
                              void* d_out, int out_size) {
    const int* user = (const int*)d_in[0];
    const int* src_pos = (const int*)d_in[1];
    const int* src_neg = (const int*)d_in[2];
    const int* tgt_pos = (const int*)d_in[3];
    const int* tgt_neg = (const int*)d_in[4];
    const unsigned* mask_s = (const unsigned*)d_in[5];
    const unsigned* mask_t = (const unsigned*)d_in[6];
    const float* su_int = (const float*)d_in[7];
    const float* si_int = (const float*)d_in[8];
    const float* tu_int = (const float*)d_in[9];
    const float* ti_int = (const float*)d_in[10];
    const float* su_pop = (const float*)d_in[11];
    const float* si_pop = (const float*)d_in[12];
    const float* tu_pop = (const float*)d_in[13];
    const float* ti_pop = (const float*)d_in[14];
    const int* s_rows = (const int*)d_in[15];
    const int* s_cols = (const int*)d_in[16];
    const float* s_vals = (const float*)d_in[17];
    const int* t_rows = (const int*)d_in[18];
    const int* t_cols = (const int*)d_in[19];
    const float* t_vals = (const float*)d_in[20];
    const float* drop_s_int = (const float*)d_in[21];
    const float* drop_t_int = (const float*)d_in[22];
    const float* drop_s_pop = (const float*)d_in[23];
    const float* drop_t_pop = (const float*)d_in[24];

    int nnz_s = in_sizes[15];
    int nnz_t = in_sizes[18];
    int cblocks_s = (nnz_s + 1023) / 1024;   // 4 edges/thread
    int cblocks_t = (nnz_t + 1023) / 1024;

    k_bitmap<<<(5 * BB) / 256, 256>>>(user, src_pos, src_neg, tgt_pos, tgt_neg);
    k_scatter<<<cblocks_s + cblocks_t, 256>>>(
        s_rows, s_cols, s_vals, drop_s_int, drop_s_pop,
        t_rows, t_cols, t_vals, drop_t_int, drop_t_pop,
        nnz_s, nnz_t, cblocks_s);
    k_rows<<<ROW_BLOCKS + DIS_BLOCKS, 256>>>(su_int, si_int, su_pop, si_pop,
                                             tu_int, ti_int, tu_pop, ti_pop);
    k_loss_final<<<LOSS_BLOCKS, 256>>>(
        user, src_pos, src_neg, tgt_pos, tgt_neg, mask_s, mask_t,
        su_int, si_int, tu_int, ti_int, su_pop, si_pop, tu_pop, ti_pop,
        (float*)d_out);
}

// round 17
// speedup vs baseline: 1.1324x; 1.1324x over previous
#include <cuda_runtime.h>

// ---------------- problem constants ----------------
#define U_CNT 100000
#define SI_CNT 50000
#define TI_CNT 40000
#define DD 64
#define BB 8192
#define NS (U_CNT + SI_CNT)   // 150000 rows in source graph
#define NT (U_CNT + TI_CNT)   // 140000 rows in target graph
#define NROWS (NS + NT)       // 290000
#define NSW ((NS + 31) / 32)
#define NTW ((NT + 31) / 32)
#define NW_TOT (NSW + NTW)
#define SLOTS 64
#define MAXS 24576            // max active s-rows (8192 users + 16384 items)
#define MAXT 24576            // max active t-rows
#define MAXROWS (MAXS + MAXT) // 49152; s-rows in [0,MAXS), t-rows in [MAXS,..)
#define CAP 128               // per-row bucket capacity
#define ROW_BLOCKS (MAXROWS / 8)   // 6144
#define DIS_BLOCKS (MAXROWS / 8)
#define LOSS_BLOCKS (BB / 8)

// ---------------- device scratch (zero-init at load; self-cleaned each run) ----------------
__device__ float g_agg_s_int[(size_t)NS * DD];
__device__ float g_agg_s_pop[(size_t)NS * DD];
__device__ float g_agg_t_int[(size_t)NT * DD];
__device__ float g_agg_t_pop[(size_t)NT * DD];
__device__ unsigned g_need_s[NSW];
__device__ unsigned g_need_t[NTW];
__device__ double g_accs[12 * SLOTS];
__device__ int g_cnts[3 * SLOTS];
__device__ unsigned g_done = 0;
__device__ int g_nrows_s = 0;
__device__ int g_nrows_t = 0;
__device__ int g_rowlist[MAXROWS];
__device__ int g_slot[NROWS];
__device__ int g_next[MAXROWS];
__device__ int4 g_erec[(size_t)MAXROWS * CAP];

// ---------------- helpers ----------------
__device__ __forceinline__ float wred(float v) {
#pragma unroll
    for (int o = 16; o; o >>= 1) v += __shfl_xor_sync(0xffffffffu, v, o);
    return v;
}
__device__ __forceinline__ float hred16(float v) {
#pragma unroll
    for (int o = 8; o; o >>= 1) v += __shfl_xor_sync(0xffffffffu, v, o);
    return v;
}
__device__ __forceinline__ double wredd(double v) {
#pragma unroll
    for (int o = 16; o; o >>= 1) v += __shfl_xor_sync(0xffffffffu, v, o);
    return v;
}
__device__ __forceinline__ int wredi(int v) {
#pragma unroll
    for (int o = 16; o; o >>= 1) v += __shfl_xor_sync(0xffffffffu, v, o);
    return v;
}
__device__ __forceinline__ float lsig(float x) {
    return fminf(x, 0.0f) - log1pf(expf(-fabsf(x)));
}

// warp-aggregated append into a partitioned rowlist segment
__device__ __forceinline__ void append_seg(bool newset, int gr, int* counter, int seg_base) {
    unsigned m = __ballot_sync(0xffffffffu, newset);
    if (!m) return;
    int lane = threadIdx.x & 31;
    int leader = __ffs(m) - 1;
    int base = 0;
    if (lane == leader) base = atomicAdd(counter, __popc(m));
    base = __shfl_sync(0xffffffffu, base, leader);
    if (newset) {
        int pos = seg_base + base + __popc(m & ((1u << lane) - 1u));
        g_rowlist[pos] = gr;
        g_slot[gr] = pos;
    }
}

// ---------------- kernels ----------------
__global__ void k_bitmap(const int* __restrict__ user, const int* __restrict__ sp,
                         const int* __restrict__ sn, const int* __restrict__ tp,
                         const int* __restrict__ tn) {
    int i = blockIdx.x * blockDim.x + threadIdx.x;
    int which = i / BB, j = i - which * BB;
    if (which == 0) {
        int u = user[j];
        unsigned bit = 1u << (u & 31);
        unsigned olds = atomicOr(&g_need_s[(unsigned)u >> 5], bit);
        unsigned oldt = atomicOr(&g_need_t[(unsigned)u >> 5], bit);
        append_seg(!(olds & bit), u, &g_nrows_s, 0);
        append_seg(!(oldt & bit), u + NS, &g_nrows_t, MAXS);
    } else if (which == 1) {
        int r = U_CNT + sp[j];
        unsigned bit = 1u << (r & 31);
        unsigned old = atomicOr(&g_need_s[(unsigned)r >> 5], bit);
        append_seg(!(old & bit), r, &g_nrows_s, 0);
    } else if (which == 2) {
        int r = U_CNT + sn[j];
        unsigned bit = 1u << (r & 31);
        unsigned old = atomicOr(&g_need_s[(unsigned)r >> 5], bit);
        append_seg(!(old & bit), r, &g_nrows_s, 0);
    } else if (which == 3) {
        int r = U_CNT + tp[j];
        unsigned bit = 1u << (r & 31);
        unsigned old = atomicOr(&g_need_t[(unsigned)r >> 5], bit);
        append_seg(!(old & bit), r + NS, &g_nrows_t, MAXS);
    } else {
        int r = U_CNT + tn[j];
        unsigned bit = 1u << (r & 31);
        unsigned old = atomicOr(&g_need_t[(unsigned)r >> 5], bit);
        append_seg(!(old & bit), r + NS, &g_nrows_t, MAXS);
    }
}

// scatter: 4 edges/thread; ALL 5 vector loads issued up front (MLP=5)
__global__ void __launch_bounds__(256) k_scatter(
    const int* __restrict__ rows_s, const int* __restrict__ cols_s,
    const float* __restrict__ vals_s, const float* __restrict__ dsi,
    const float* __restrict__ dsp,
    const int* __restrict__ rows_t, const int* __restrict__ cols_t,
    const float* __restrict__ vals_t, const float* __restrict__ dti,
    const float* __restrict__ dtp,
    int nnz_s, int nnz_t, int blocks_s) {

    bool is_s = (int)blockIdx.x < blocks_s;
    int bblk = is_s ? blockIdx.x : blockIdx.x - blocks_s;
    int nnz = is_s ? nnz_s : nnz_t;
    const int* __restrict__ rows = is_s ? rows_s : rows_t;
    const int* __restrict__ cols = is_s ? cols_s : cols_t;
    const float* __restrict__ vals = is_s ? vals_s : vals_t;
    const float* __restrict__ dint = is_s ? dsi : dti;
    const float* __restrict__ dpop = is_s ? dsp : dtp;
    const unsigned* __restrict__ need = is_s ? g_need_s : g_need_t;
    int gbase = is_s ? 0 : NS;

    int i4 = (bblk * 256 + threadIdx.x) * 4;
    if (i4 + 4 <= nnz) {
        int4 r4 = *(const int4*)(rows + i4);
        int4 c4 = *(const int4*)(cols + i4);
        float4 v4 = *(const float4*)(vals + i4);
        float4 di4 = *(const float4*)(dint + i4);
        float4 dp4 = *(const float4*)(dpop + i4);
        bool act[4];
        act[0] = (need[(unsigned)r4.x >> 5] >> (r4.x & 31)) & 1u;
        act[1] = (need[(unsigned)r4.y >> 5] >> (r4.y & 31)) & 1u;
        act[2] = (need[(unsigned)r4.z >> 5] >> (r4.z & 31)) & 1u;
        act[3] = (need[(unsigned)r4.w >> 5] >> (r4.w & 31)) & 1u;
#pragma unroll
        for (int k = 0; k < 4; k++) {
            if (!act[k]) continue;
            int slot = g_slot[(&r4.x)[k] + gbase];
            int pos = atomicAdd(&g_next[slot], 1);
            if (pos < CAP) {
                int4 rec;
                rec.x = (&c4.x)[k];
                rec.y = __float_as_int((&v4.x)[k] * (&di4.x)[k]);
                rec.z = __float_as_int((&v4.x)[k] * (&dp4.x)[k]);
                rec.w = 0;
                g_erec[(size_t)slot * CAP + pos] = rec;
            }
        }
    } else {
        for (int k = 0; k < 4; k++) {
            int i = i4 + k;
            if (i >= nnz) break;
            int r = rows[i];
            if (!((need[(unsigned)r >> 5] >> (r & 31)) & 1u)) continue;
            int slot = g_slot[r + gbase];
            int pos = atomicAdd(&g_next[slot], 1);
            if (pos < CAP) {
                float v = vals[i];
                int4 rec;
                rec.x = cols[i];
                rec.y = __float_as_int(v * dint[i]);
                rec.z = __float_as_int(v * dpop[i]);
                rec.w = 0;
                g_erec[(size_t)slot * CAP + pos] = rec;
            }
        }
    }
}

// fused: row aggregation (blocks [0, ROW_BLOCKS); s-rows first then t-rows,
// each phase's tables fit in L2) + dis over rowlist + bitmap self-clean.
__global__ void __launch_bounds__(256) k_rows(
    const float* __restrict__ su_i, const float* __restrict__ si_i,
    const float* __restrict__ su_p, const float* __restrict__ si_p,
    const float* __restrict__ tu_i, const float* __restrict__ ti_i,
    const float* __restrict__ tu_p, const float* __restrict__ ti_p) {

    int lane = threadIdx.x & 31;
    int wid = threadIdx.x >> 5;

    if ((int)blockIdx.x >= ROW_BLOCKS) {
        // ---- dis blocks: masked-L1 over rowlist + bitmap clear ----
        int db = blockIdx.x - ROW_BLOCKS;
        {
            int ci = db * 256 + threadIdx.x;
            if (ci < NSW) g_need_s[ci] = 0u;
            else if (ci < NW_TOT) g_need_t[ci - NSW] = 0u;
        }
        int gw = db * 8 + wid;
        bool valid = (gw < MAXS) ? (gw < g_nrows_s) : (gw - MAXS < g_nrows_t);
        if (!valid) return;
        int gr = g_rowlist[gw];
        int slot = gw & (SLOTS - 1);
        if (gr < U_CNT) {
            int rr = gr;
            float2 a = ((const float2*)(su_i + (size_t)rr * DD))[lane];
            float2 b = ((const float2*)(su_p + (size_t)rr * DD))[lane];
            float2 cc = ((const float2*)(tu_i + (size_t)rr * DD))[lane];
            float2 d = ((const float2*)(tu_p + (size_t)rr * DD))[lane];
            float s1 = wred(fabsf(a.x - b.x) + fabsf(a.y - b.y));
            float s2 = wred(fabsf(cc.x - d.x) + fabsf(cc.y - d.y));
            if (lane == 0) {
                atomicAdd(&g_accs[8 * SLOTS + slot], (double)s1);
                atomicAdd(&g_accs[10 * SLOTS + slot], (double)s2);
                atomicAdd(&g_cnts[0 * SLOTS + slot], 1);
            }
        } else if (gr < NS) {
            int it = gr - U_CNT;
            float2 a = ((const float2*)(si_i + (size_t)it * DD))[lane];
            float2 b = ((const float2*)(si_p + (size_t)it * DD))[lane];
            float s = wred(fabsf(a.x - b.x) + fabsf(a.y - b.y));
            if (lane == 0) {
                atomicAdd(&g_accs[9 * SLOTS + slot], (double)s);
                atomicAdd(&g_cnts[1 * SLOTS + slot], 1);
            }
        } else if (gr >= NS + U_CNT) {
            int it = gr - NS - U_CNT;
            float2 a = ((const float2*)(ti_i + (size_t)it * DD))[lane];
            float2 b = ((const float2*)(ti_p + (size_t)it * DD))[lane];
            float s = wred(fabsf(a.x - b.x) + fabsf(a.y - b.y));
            if (lane == 0) {
                atomicAdd(&g_accs[11 * SLOTS + slot], (double)s);
                atomicAdd(&g_cnts[2 * SLOTS + slot], 1);
            }
        }
        return;
    }

    // ---- row aggregation blocks (proven gather loop; graph-partitioned order) ----
    int gw = blockIdx.x * 8 + wid;
    bool valid = (gw < MAXS) ? (gw < g_nrows_s) : (gw - MAXS < g_nrows_t);
    if (!valid) return;
    int half = lane >> 4, sub = lane & 15;

    int gr = g_rowlist[gw];
    bool is_s = gr < NS;
    int row = is_s ? gr : gr - NS;
    int cnt = min(g_next[gw], CAP);
    if (lane == 0) g_next[gw] = 0;   // self-clean for next replay
    const int4* __restrict__ bucket = g_erec + (size_t)gw * CAP;

    const float* u_tab = is_s ? (half ? su_p : su_i) : (half ? tu_p : tu_i);
    const float* i_tab = is_s ? (half ? si_p : si_i) : (half ? ti_p : ti_i);
    float* agg = is_s ? (half ? g_agg_s_pop : g_agg_s_int)
                      : (half ? g_agg_t_pop : g_agg_t_int);

    float4 acc = make_float4(0.f, 0.f, 0.f, 0.f);

    for (int chunk = 0; chunk < cnt; chunk += 32) {
        int nc = min(32, cnt - chunk);
        int4 rec = (lane < nc) ? bucket[chunk + lane] : make_int4(0, 0, 0, 0);
        int e = 0;
        for (; e + 4 <= nc; e += 4) {
#pragma unroll
            for (int j = 0; j < 4; j++) {
                int s = e + j;
                int c = __shfl_sync(0xffffffffu, rec.x, s);
                int wz = __shfl_sync(0xffffffffu, rec.y, s);
                int ww = __shfl_sync(0xffffffffu, rec.z, s);
                float w = __int_as_float(half ? ww : wz);
                const float* tab = (c < U_CNT) ? u_tab : i_tab;
                int cr = (c < U_CNT) ? c : c - U_CNT;
                float4 ev = __ldg(((const float4*)(tab + (size_t)cr * DD)) + sub);
                acc.x += w * ev.x; acc.y += w * ev.y;
                acc.z += w * ev.z; acc.w += w * ev.w;
            }
        }
        for (; e < nc; e++) {
            int c = __shfl_sync(0xffffffffu, rec.x, e);
            int wz = __shfl_sync(0xffffffffu, rec.y, e);
            int ww = __shfl_sync(0xffffffffu, rec.z, e);
            float w = __int_as_float(half ? ww : wz);
            const float* tab = (c < U_CNT) ? u_tab : i_tab;
            int cr = (c < U_CNT) ? c : c - U_CNT;
            float4 ev = __ldg(((const float4*)(tab + (size_t)cr * DD)) + sub);
            acc.x += w * ev.x; acc.y += w * ev.y;
            acc.z += w * ev.z; acc.w += w * ev.w;
        }
    }
    ((float4*)(agg + (size_t)row * DD))[sub] = acc;
}

// loss: warp per sample, half-warp per factor (R15-proven form).
__global__ void __launch_bounds__(256) k_loss_final(
    const int* __restrict__ user, const int* __restrict__ spi,
    const int* __restrict__ sni, const int* __restrict__ tpi,
    const int* __restrict__ tni,
    const unsigned* __restrict__ mask_s, const unsigned* __restrict__ mask_t,
    const float* __restrict__ su_i, const float* __restrict__ si_i,
    const float* __restrict__ tu_i, const float* __restrict__ ti_i,
    const float* __restrict__ su_p, const float* __restrict__ si_p,
    const float* __restrict__ tu_p, const float* __restrict__ ti_p,
    float* __restrict__ out) {

    int lane = threadIdx.x & 31;
    int wid = threadIdx.x >> 5;
    int half = lane >> 4, sub = lane & 15;
    __shared__ double s_rows[12];
    __shared__ int s_cnt[3];
    __shared__ int s_last;

    {
        int w = blockIdx.x * 8 + wid;
        int u = user[w], ps = spi[w], ns = sni[w], pt = tpi[w], nt = tni[w];

        const float* suT = half ? su_p : su_i;
        const float* siT = half ? si_p : si_i;
        const float* tuT = half ? tu_p : tu_i;
        const float* tiT = half ? ti_p : ti_i;
        const float* aggSU = half ? g_agg_s_pop : g_agg_s_int;
        const float* aggTU = half ? g_agg_t_pop : g_agg_t_int;

#define GET4(t, row) (((const float4*)((t) + (size_t)(row) * DD))[sub])
        float4 e_us = GET4(suT, u);
        float4 a_us = GET4(aggSU, u);
        float4 e_ut = GET4(tuT, u);
        float4 a_ut = GET4(aggTU, u);
        float4 e_ip = GET4(siT, ps);
        float4 a_ip = GET4(aggSU, U_CNT + ps);
        float4 e_in = GET4(siT, ns);
        float4 a_in = GET4(aggSU, U_CNT + ns);
        float4 e_jp = GET4(tiT, pt);
        float4 a_jp = GET4(aggTU, U_CNT + pt);
        float4 e_jn = GET4(tiT, nt);
        float4 a_jn = GET4(aggTU, U_CNT + nt);
#undef GET4
        auto mk4 = [](float4 a, float4 b) {
            return make_float4(0.5f * (a.x + b.x), 0.5f * (a.y + b.y),
                               0.5f * (a.z + b.z), 0.5f * (a.w + b.w));
        };
        auto d4 = [](float4 a, float4 b) {
            return a.x * b.x + a.y * b.y + a.z * b.z + a.w * b.w;
        };
        float4 us = mk4(e_us, a_us);
        float4 ut = mk4(e_ut, a_ut);
        float4 ip = mk4(e_ip, a_ip);
        float4 in_ = mk4(e_in, a_in);
        float4 jp = mk4(e_jp, a_jp);
        float4 jn = mk4(e_jn, a_jn);

        float sp = hred16(d4(us, ip));
        float sn = hred16(d4(us, in_));
        float tp = hred16(d4(ut, jp));
        float tn = hred16(d4(ut, jn));

        float sp_p = __shfl_sync(0xffffffffu, sp, 16);
        float sn_p = __shfl_sync(0xffffffffu, sn, 16);
        float tp_p = __shfl_sync(0xffffffffu, tp, 16);
        float tn_p = __shfl_sync(0xffffffffu, tn, 16);

        if (lane == 0) {
            float sp_i = sp, sn_i = sn, tp_i = tp, tn_i = tn;
            int slot = w & (SLOTS - 1);
            float mS = (mask_s[w] != 0u) ? 1.f : 0.f;
            float mT = (mask_t[w] != 0u) ? 1.f : 0.f;

            float t0 = mS * lsig(sp_i - sn_i);
            float t3 = mT * lsig(tp_i - tn_i);
            float xs = sn_p - sp_p;
            float cs = log1pf(expf(-fabsf(xs)));
            float t12 = mS * fminf(xs, 0.f) + (1.f - mS) * fminf(-xs, 0.f) - cs;
            float xt = tn_p - tp_p;
            float ct = log1pf(expf(-fabsf(xt)));
            float t45 = mT * fminf(xt, 0.f) + (1.f - mT) * fminf(-xt, 0.f) - ct;
            float t6 = lsig((sp_i + sp_p) - (sn_i + sn_p));
            float t7 = lsig((tp_i + tp_p) - (tn_i + tn_p));

            atomicAdd(&g_accs[0 * SLOTS + slot], (double)t0);
            atomicAdd(&g_accs[1 * SLOTS + slot], (double)t12);
            atomicAdd(&g_accs[3 * SLOTS + slot], (double)t3);
            atomicAdd(&g_accs[4 * SLOTS + slot], (double)t45);
            atomicAdd(&g_accs[6 * SLOTS + slot], (double)t6);
            atomicAdd(&g_accs[7 * SLOTS + slot], (double)t7);
        }
    }

    // ---- last-block final reduction + state cleanup ----
    __syncthreads();
    if (threadIdx.x == 0) {
        __threadfence();
        unsigned t = atomicInc(&g_done, gridDim.x - 1);
        s_last = (t == gridDim.x - 1) ? 1 : 0;
    }
    __syncthreads();
    if (!s_last) return;

    {
        double v = g_accs[wid * SLOTS + lane] + g_accs[wid * SLOTS + 32 + lane];
        v = wredd(v);
        if (lane == 0) s_rows[wid] = v;
        if (wid < 4) {
            int row = wid + 8;
            double v2 = g_accs[row * SLOTS + lane] + g_accs[row * SLOTS + 32 + lane];
            v2 = wredd(v2);
            if (lane == 0) s_rows[row] = v2;
        }
        if (wid >= 5 && wid < 8) {
            int cr = wid - 5;
            int cv = g_cnts[cr * SLOTS + lane] + g_cnts[cr * SLOTS + 32 + lane];
            cv = wredi(cv);
            if (lane == 0) s_cnt[cr] = cv;
        }
    }
    __syncthreads();
    for (int i = threadIdx.x; i < 12 * SLOTS; i += blockDim.x) g_accs[i] = 0.0;
    for (int i = threadIdx.x; i < 3 * SLOTS; i += blockDim.x) g_cnts[i] = 0;
    if (threadIdx.x == 0) {
        g_nrows_s = 0;
        g_nrows_t = 0;
        double Bn = (double)BB;
        double li_s = -s_rows[0] / Bn, lp_s = -(s_rows[1] + s_rows[2]) / Bn;
        double li_t = -s_rows[3] / Bn, lp_t = -(s_rows[4] + s_rows[5]) / Bn;
        double lt_s = -s_rows[6] / Bn, lt_t = -s_rows[7] / Bn;
        double cu = (double)(s_cnt[0] > 1 ? s_cnt[0] : 1);
        double cs = (double)(s_cnt[1] > 1 ? s_cnt[1] : 1);
        double ct = (double)(s_cnt[2] > 1 ? s_cnt[2] : 1);
        double dis = s_rows[8] / (cu * DD) + s_rows[9] / (cs * DD)
                   + s_rows[10] / (cu * DD) + s_rows[11] / (ct * DD);
        double loss = lt_s + lt_t + 0.1 * (li_s + li_t) + 0.1 * (lp_s + lp_t) - 0.01 * dis;
        out[0] = (float)loss;
    }
}

// ---------------- launch ----------------
extern "C" void kernel_launch(void* const* d_in, const int* in_sizes, int n_in,
                              void* d_out, int out_size) {
    const int* user = (const int*)d_in[0];
    const int* src_pos = (const int*)d_in[1];
    const int* src_neg = (const int*)d_in[2];
    const int* tgt_pos = (const int*)d_in[3];
    const int* tgt_neg = (const int*)d_in[4];
    const unsigned* mask_s = (const unsigned*)d_in[5];
    const unsigned* mask_t = (const unsigned*)d_in[6];
    const float* su_int = (const float*)d_in[7];
    const float* si_int = (const float*)d_in[8];
    const float* tu_int = (const float*)d_in[9];
    const float* ti_int = (const float*)d_in[10];
    const float* su_pop = (const float*)d_in[11];
    const float* si_pop = (const float*)d_in[12];
    const float* tu_pop = (const float*)d_in[13];
    const float* ti_pop = (const float*)d_in[14];
    const int* s_rows = (const int*)d_in[15];
    const int* s_cols = (const int*)d_in[16];
    const float* s_vals = (const float*)d_in[17];
    const int* t_rows = (const int*)d_in[18];
    const int* t_cols = (const int*)d_in[19];
    const float* t_vals = (const float*)d_in[20];
    const float* drop_s_int = (const float*)d_in[21];
    const float* drop_t_int = (const float*)d_in[22];
    const float* drop_s_pop = (const float*)d_in[23];
    const float* drop_t_pop = (const float*)d_in[24];

    int nnz_s = in_sizes[15];
    int nnz_t = in_sizes[18];
    int cblocks_s = (nnz_s + 1023) / 1024;   // 4 edges/thread
    int cblocks_t = (nnz_t + 1023) / 1024;

    k_bitmap<<<(5 * BB) / 256, 256>>>(user, src_pos, src_neg, tgt_pos, tgt_neg);
    k_scatter<<<cblocks_s + cblocks_t, 256>>>(
        s_rows, s_cols, s_vals, drop_s_int, drop_s_pop,
        t_rows, t_cols, t_vals, drop_t_int, drop_t_pop,
        nnz_s, nnz_t, cblocks_s);
    k_rows<<<ROW_BLOCKS + DIS_BLOCKS, 256>>>(su_int, si_int, su_pop, si_pop,
                                             tu_int, ti_int, tu_pop, ti_pop);
    k_loss_final<<<LOSS_BLOCKS, 256>>>(
        user, src_pos, src_neg, tgt_pos, tgt_neg, mask_s, mask_t,
        su_int, si_int, tu_int, ti_int, su_pop, si_pop, tu_pop, ti_pop,
        (float*)d_out);
}